// round 11
// baseline (speedup 1.0000x reference)
#include <cuda_runtime.h>
#include <cuda_fp16.h>
#include <math_constants.h>
#include <cstdint>

// ---------------- problem constants ----------------
#define B_     32
#define S_     64
#define E_     128
#define TSTEP  256
#define VOCAB  32000
#define ROWS   8192
#define NCHUNK 250            // vocab chunks of 128
#define GRP    10             // chunks per work unit
#define NGRP   25             // units per mtile
#define NUNITS 1600           // 64 mtiles * 25
#define NCTA   148
#define NSLOT  (NGRP*4)       // (group, warp_n) partial slots
#define L2E    1.4426950408889634f

// ---------------- scratch ----------------
__device__ float    g_xtran [B_*S_*S_];
__device__ float    g_M2    [2][B_*S_*S_];       // ping-pong M^(2^k)
__device__ unsigned g_sync  [B_];                // per-batch iteration counters
__device__ float    g_A     [B_*TSTEP*S_];
__device__ float    g_zs    [ROWS*E_];
__device__ float    g_bl2   [VOCAB];             // bias*L2E + (127 - 30*L2E)
__device__ __align__(16) unsigned short g_w16[VOCAB*E_];
__device__ __align__(16) unsigned short g_z16[ROWS*E_];
__device__ __align__(16) float g_epsG[NSLOT*ROWS];
__device__ float    g_tg [ROWS];

// ---------------- helpers ----------------
__device__ __forceinline__ uint32_t smem_u32b(const void* p) {
    uint32_t a;
    asm("{ .reg .u64 t; cvta.to.shared.u64 t, %1; cvt.u32.u64 %0, t; }" : "=r"(a) : "l"(p));
    return a;
}
__device__ __forceinline__ void cpa16(uint32_t dst, const void* src) {
    asm volatile("cp.async.cg.shared.global [%0], [%1], 16;" :: "r"(dst), "l"(src));
}
#define CP_COMMIT() asm volatile("cp.async.commit_group;" ::: "memory")
#define CP_WAIT1()  asm volatile("cp.async.wait_group 1;" ::: "memory")

__device__ __forceinline__ void ldm_x4(uint32_t addr, uint32_t& r0, uint32_t& r1, uint32_t& r2, uint32_t& r3) {
    asm volatile("ldmatrix.sync.aligned.m8n8.x4.shared.b16 {%0,%1,%2,%3}, [%4];"
        : "=r"(r0), "=r"(r1), "=r"(r2), "=r"(r3) : "r"(addr));
}
__device__ __forceinline__ void ldm_x2(uint32_t addr, uint32_t& r0, uint32_t& r1) {
    asm volatile("ldmatrix.sync.aligned.m8n8.x2.shared.b16 {%0,%1}, [%2];"
        : "=r"(r0), "=r"(r1) : "r"(addr));
}
// fp16-accumulate HMMA (2 result regs)
__device__ __forceinline__ void mma16816h(uint32_t* d, const uint32_t* a, const uint32_t* b) {
    asm volatile("mma.sync.aligned.m16n8k16.row.col.f16.f16.f16.f16 "
        "{%0,%1}, {%2,%3,%4,%5}, {%6,%7}, {%0,%1};"
        : "+r"(d[0]), "+r"(d[1])
        : "r"(a[0]), "r"(a[1]), "r"(a[2]), "r"(a[3]), "r"(b[0]), "r"(b[1]));
}

typedef unsigned long long u64t;
__device__ __forceinline__ u64t pk2(float lo, float hi) {
    u64t r; asm("mov.b64 %0, {%1, %2};" : "=l"(r) : "f"(lo), "f"(hi)); return r;
}
__device__ __forceinline__ u64t fma2v(u64t a, u64t b, u64t c) {
    u64t r; asm volatile("fma.rn.f32x2 %0, %1, %2, %3;" : "=l"(r) : "l"(a), "l"(b), "l"(c)); return r;
}
__device__ __forceinline__ u64t h2f2(uint32_t h) {
    __half2 hh = *(__half2*)&h;
    float2 f = __half22float2(hh);
    u64t r; asm("mov.b64 %0, {%1, %2};" : "=l"(r) : "f"(f.x), "f"(f.y));
    return r;
}

struct ExpC {
    u64t L2E2, MG2, NEG1, C4, C3, C2, C1, ONE2;
};
// packed exp(l-30) accumulate; bl2 pre-biased: bias*L2E + (127 - 30*L2E)
__device__ __forceinline__ void expacc2(u64t acc, u64t bl2, const ExpC& K, u64t& rs) {
    u64t y = fma2v(acc, K.L2E2, bl2);
    u64t t = fma2v(y, K.ONE2, K.MG2);        // y + magic
    u64t n = fma2v(K.MG2, K.NEG1, t);        // t - magic
    u64t f = fma2v(n, K.NEG1, y);            // y - n
    u64t p = fma2v(K.C4, f, K.C3);
    p = fma2v(p, f, K.C2);
    p = fma2v(p, f, K.C1);
    p = fma2v(p, f, K.ONE2);
    uint32_t t0, t1;
    asm("mov.b64 {%0, %1}, %2;" : "=r"(t0), "=r"(t1) : "l"(t));
    t0 <<= 23; t1 <<= 23;
    u64t sc; asm("mov.b64 %0, {%1, %2};" : "=l"(sc) : "r"(t0), "r"(t1));
    rs = fma2v(p, sc, rs);
}

// ================= Kernel A12: scores + softmax + att0 (fused), counter reset =========
#define KA12_SMEM ((8256 + 4160) * 4)
__global__ __launch_bounds__(256) void kA12(const float* __restrict__ latent,
                                            const int* __restrict__ zi) {
    extern __shared__ float s[];
    float* xkS = s;            // 64 x 129
    float* scS = s + 8256;     // 64 x 65 (scores, [s][t])
    __shared__ float smv[64];
    int b = blockIdx.x, tid = threadIdx.x;
    const float* xq = latent + (size_t)zi[(b >> 2)]     * 32768 + (size_t)(b & 3) * 8192;
    const float* xk = latent + (size_t)zi[8 + (b >> 2)] * 32768 + (size_t)(b & 3) * 8192;

    if (tid == 0) g_sync[b] = 0u;     // reset scan sync counter (each replay)

    for (int idx = tid; idx < 8192; idx += 256)
        xkS[(idx >> 7) * 129 + (idx & 127)] = __ldg(xk + idx);
    __syncthreads();

    int t = tid & 63, sg = tid >> 6;
    for (int i = 0; i < 16; i++) {
        int ss = sg + 4 * i;
        float a0 = 0.f, a1 = 0.f, a2 = 0.f, a3 = 0.f;
        const float4* qp = (const float4*)(xq + ss * 128);
        #pragma unroll 8
        for (int e4 = 0; e4 < 32; e4++) {
            float4 q = __ldg(qp + e4);
            const float* kp = &xkS[t * 129 + e4 * 4];
            a0 = fmaf(q.x, kp[0], a0);
            a1 = fmaf(q.y, kp[1], a1);
            a2 = fmaf(q.z, kp[2], a2);
            a3 = fmaf(q.w, kp[3], a3);
        }
        scS[ss * 65 + t] = ((a0 + a1) + (a2 + a3)) * 0.08838834764831843f;
    }
    __syncthreads();

    // column softmax over s (threads 0..63, one column each)
    if (tid < 64) {
        float mx = -CUDART_INF_F;
        for (int ss = 0; ss < 64; ss++) mx = fmaxf(mx, scS[ss * 65 + tid]);
        float sum = 0.f;
        for (int ss = 0; ss < 64; ss++) {
            float e = __expf(scS[ss * 65 + tid] - mx);
            scS[ss * 65 + tid] = e;
            sum += e;
        }
        float inv = 1.f / sum;
        for (int ss = 0; ss < 64; ss++)
            g_xtran[b * 4096 + ss * 64 + tid] = scS[ss * 65 + tid] * inv;
    }

    // att0 = softmax over s of xi[b][s][0]
    const float* ip = latent + (size_t)zi[24 + (b >> 2)] * 32768 + (size_t)(b & 3) * 8192;
    float xi = 0.f;
    if (tid < 64) { xi = __ldg(ip + tid * 128); smv[tid] = xi; }
    __syncthreads();
    float m2 = -CUDART_INF_F;
    if (tid < 64) { for (int ss = 0; ss < 64; ss++) m2 = fmaxf(m2, smv[ss]); }
    float e2 = (tid < 64) ? __expf(xi - m2) : 0.f;
    __syncthreads();
    if (tid < 64) smv[tid] = e2;
    __syncthreads();
    if (tid < 64) {
        float su = 0.f;
        for (int ss = 0; ss < 64; ss++) su += smv[ss];
        g_A[(size_t)b * 16384 + tid] = e2 / su;   // A[0] = att0
    }
}

// ---- 64-dots with 8 independent accumulator chains ----
__device__ __forceinline__ float dotS68(const float* __restrict__ row, const float* mcol) {
    float a0=0.f,a1=0.f,a2=0.f,a3=0.f,a4=0.f,a5=0.f,a6=0.f,a7=0.f;
    #pragma unroll
    for (int ss = 0; ss < 64; ss += 8) {
        float4 x = *(const float4*)&row[ss];
        float4 y = *(const float4*)&row[ss + 4];
        a0 = fmaf(x.x, mcol[ss+0], a0);
        a1 = fmaf(x.y, mcol[ss+1], a1);
        a2 = fmaf(x.z, mcol[ss+2], a2);
        a3 = fmaf(x.w, mcol[ss+3], a3);
        a4 = fmaf(y.x, mcol[ss+4], a4);
        a5 = fmaf(y.y, mcol[ss+5], a5);
        a6 = fmaf(y.z, mcol[ss+6], a6);
        a7 = fmaf(y.w, mcol[ss+7], a7);
    }
    return ((a0 + a1) + (a2 + a3)) + ((a4 + a5) + (a6 + a7));
}
__device__ __forceinline__ float dotG64(const float* __restrict__ row, const float* mcol) {
    float a0=0.f,a1=0.f,a2=0.f,a3=0.f,a4=0.f,a5=0.f,a6=0.f,a7=0.f;
    const float4* rp = (const float4*)row;
    #pragma unroll
    for (int ss = 0; ss < 64; ss += 8) {
        float4 x = __ldg(rp + (ss >> 2));
        float4 y = __ldg(rp + (ss >> 2) + 1);
        a0 = fmaf(x.x, mcol[ss+0], a0);
        a1 = fmaf(x.y, mcol[ss+1], a1);
        a2 = fmaf(x.z, mcol[ss+2], a2);
        a3 = fmaf(x.w, mcol[ss+3], a3);
        a4 = fmaf(y.x, mcol[ss+4], a4);
        a5 = fmaf(y.y, mcol[ss+5], a5);
        a6 = fmaf(y.z, mcol[ss+6], a6);
        a7 = fmaf(y.w, mcol[ss+7], a7);
    }
    return ((a0 + a1) + (a2 + a3)) + ((a4 + a5) + (a6 + a7));
}

// ================= Kernel BS: 4-way parallel log-doubling scan =================
// grid (32, 4): batch b, column quarter q (16 cols). Cross-CTA sync via g_sync[b].
// M ping-pong lives in global; M loads use __ldcg (L1 not coherent across SMs).
__global__ __launch_bounds__(256) void kBS() {
    __shared__ float Ms[64 * 68];
    int b = blockIdx.x, q = blockIdx.y, tid = threadIdx.x;
    int colq = q * 16 + (tid & 15);
    int r0 = tid >> 4;                   // 0..15
    int cur = 1;

    #pragma unroll 1
    for (int it = 0; it < 8; it++) {
        const float* src = (it == 0) ? (g_xtran + b * 4096)
                                     : (g_M2[(it - 1) & 1] + b * 4096);
        #pragma unroll
        for (int k = 0; k < 4; k++) {
            int i4 = tid + k * 256;                       // float4 index (1024 total)
            float4 v = __ldcg((const float4*)src + i4);
            int row = i4 >> 4, col = (i4 & 15) * 4;
            *(float4*)&Ms[row * 68 + col] = v;
        }
        __syncthreads();

        float mcol[64];
        #pragma unroll
        for (int ss = 0; ss < 64; ss++) mcol[ss] = Ms[ss * 68 + colq];

        if (it < 7) {                                     // squaring slab (16 cols)
            float* dst = g_M2[it & 1] + b * 4096;
            #pragma unroll
            for (int rr = 0; rr < 4; rr++) {
                int r = r0 + rr * 16;
                dst[r * 64 + colq] = dotS68(&Ms[r * 68], mcol);
            }
        }
        #pragma unroll 1
        for (int r = r0; r < cur; r += 16) {              // extension slab
            g_A[(size_t)b * 16384 + (size_t)(cur + r) * 64 + colq] =
                dotG64(g_A + (size_t)b * 16384 + (size_t)r * 64, mcol);
        }

        if (it < 7) {
            __threadfence();
            __syncthreads();
            if (tid == 0) {
                atomicAdd(&g_sync[b], 1u);
                while (atomicAdd(&g_sync[b], 0u) < 4u * (unsigned)(it + 1)) { }
            }
            __syncthreads();
        }
        cur <<= 1;
    }
}

// ================= Kernel B2: zs = A * xv, + fp16 convert =================
__global__ __launch_bounds__(256) void kB2(const float* __restrict__ latent, const int* __restrict__ zi) {
    __shared__ float As[2048];
    __shared__ float xvS[8192];
    int b = blockIdx.x >> 3, tb = blockIdx.x & 7;
    int tid = threadIdx.x;
    const float* xv = latent + (size_t)zi[16 + (b >> 2)] * 32768 + (size_t)(b & 3) * 8192;
    for (int i = tid; i < 8192; i += 256) xvS[i] = __ldg(xv + i);
    for (int i = tid; i < 2048; i += 256) As[i] = g_A[(size_t)(b * 256 + tb * 32) * 64 + i];
    __syncthreads();
    int e = tid & 127, h = tid >> 7;
    for (int i = 0; i < 16; i++) {
        int tl = h * 16 + i;
        float a0 = 0.f, a1 = 0.f, a2 = 0.f, a3 = 0.f;
        #pragma unroll
        for (int s2 = 0; s2 < 64; s2 += 4) {
            a0 = fmaf(As[tl * 64 + s2 + 0], xvS[(s2 + 0) * 128 + e], a0);
            a1 = fmaf(As[tl * 64 + s2 + 1], xvS[(s2 + 1) * 128 + e], a1);
            a2 = fmaf(As[tl * 64 + s2 + 2], xvS[(s2 + 2) * 128 + e], a2);
            a3 = fmaf(As[tl * 64 + s2 + 3], xvS[(s2 + 3) * 128 + e], a3);
        }
        float acc = (a0 + a1) + (a2 + a3);
        size_t row = (size_t)b * 256 + tb * 32 + tl;
        g_zs[row * 128 + e] = acc;
        g_z16[row * 128 + e] = __half_as_ushort(__float2half(acc));
    }
}

// ================= Kernel Wc: vocab fp16 + bl2 precompute + g_epsG zero =================
__global__ __launch_bounds__(256) void kWc(const float* __restrict__ vw,
                                           const float* __restrict__ vb) {
    int t = blockIdx.x * 256 + threadIdx.x;
    size_t i = (size_t)t * 8;
    float4 a = *(const float4*)(vw + i);
    float4 b = *(const float4*)(vw + i + 4);
    __half2 h0 = __floats2half2_rn(a.x, a.y);
    __half2 h1 = __floats2half2_rn(a.z, a.w);
    __half2 h2 = __floats2half2_rn(b.x, b.y);
    __half2 h3 = __floats2half2_rn(b.z, b.w);
    uint4 o;
    o.x = *(uint32_t*)&h0; o.y = *(uint32_t*)&h1;
    o.z = *(uint32_t*)&h2; o.w = *(uint32_t*)&h3;
    *(uint4*)(g_w16 + i) = o;
    if (t < VOCAB) g_bl2[t] = fmaf(__ldg(vb + t), L2E, 127.0f - 30.f * L2E);
    if (t < (NSLOT * ROWS) / 4) {
        float4 z = {0.f, 0.f, 0.f, 0.f};
        ((float4*)g_epsG)[t] = z;
    }
}

// ================= Kernel T: exact fp32 target logits =================
__global__ __launch_bounds__(256) void kT(const float* __restrict__ vw,
                                          const float* __restrict__ vb,
                                          const int*   __restrict__ y) {
    int r = blockIdx.x * 8 + (threadIdx.x >> 5);
    int lane = threadIdx.x & 31;
    int t = __ldg(y + r);
    float4 z = *(const float4*)(g_zs + (size_t)r * 128 + lane * 4);
    float4 w = *(const float4*)(vw + (size_t)t * 128 + lane * 4);
    float d = z.x * w.x + z.y * w.y + z.z * w.z + z.w * w.w;
    #pragma unroll
    for (int off = 16; off; off >>= 1) d += __shfl_xor_sync(0xffffffffu, d, off);
    if (lane == 0) g_tg[r] = d + __ldg(vb + t);
}

// ================= Kernel C4: persistent segment-scheduled HMMA + poly-exp ==========
#define PITCH   272
#define SM_A    0
#define SM_B0   34816
#define SMEM_KC 104448

template<bool DO_EPI>
__device__ __forceinline__ void do_chunk(uint32_t aBase, uint32_t Bbase,
                                         uint32_t (&hdN)[4][4][2],
                                         uint32_t (&hdO)[4][4][2],
                                         const float* __restrict__ bl2c,
                                         int warp_n, int lane,
                                         const ExpC& K, u64t (&RS)[8]) {
    #pragma unroll
    for (int mt = 0; mt < 4; mt++)
        #pragma unroll
        for (int nt = 0; nt < 4; nt++) { hdN[mt][nt][0] = 0u; hdN[mt][nt][1] = 0u; }

    u64t bv[4];
    if (DO_EPI) {
        #pragma unroll
        for (int nt = 0; nt < 4; nt++)
            bv[nt] = *(const u64t*)&bl2c[warp_n * 32 + nt * 8 + (lane & 3) * 2];
    }

    #pragma unroll
    for (int ks = 0; ks < 8; ks++) {
        uint32_t a[4][4], b[4][2];
        #pragma unroll
        for (int mt = 0; mt < 4; mt++)
            ldm_x4(aBase + (uint32_t)(mt * 16) * PITCH + (uint32_t)(ks * 32),
                   a[mt][0], a[mt][1], a[mt][2], a[mt][3]);
        #pragma unroll
        for (int nt = 0; nt < 4; nt++)
            ldm_x2(Bbase + (uint32_t)(nt * 8) * PITCH + (uint32_t)(ks * 32),
                   b[nt][0], b[nt][1]);
        #pragma unroll
        for (int mt = 0; mt < 4; mt++)
            #pragma unroll
            for (int nt = 0; nt < 4; nt++)
                mma16816h(hdN[mt][nt], a[mt], b[nt]);
        if (DO_EPI) {
            #pragma unroll
            for (int f = ks * 2; f < ks * 2 + 2; f++) {
                int mt = f >> 2, nt = f & 3;
                expacc2(h2f2(hdO[mt][nt][0]), bv[nt], K, RS[mt * 2 + 0]);
                expacc2(h2f2(hdO[mt][nt][1]), bv[nt], K, RS[mt * 2 + 1]);
            }
        }
    }
}

__device__ __forceinline__ void epi_only(uint32_t (&hdO)[4][4][2],
                                         const float* __restrict__ bl2c,
                                         int warp_n, int lane,
                                         const ExpC& K, u64t (&RS)[8]) {
    #pragma unroll
    for (int nt = 0; nt < 4; nt++) {
        u64t bv = *(const u64t*)&bl2c[warp_n * 32 + nt * 8 + (lane & 3) * 2];
        #pragma unroll
        for (int mt = 0; mt < 4; mt++) {
            expacc2(h2f2(hdO[mt][nt][0]), bv, K, RS[mt * 2 + 0]);
            expacc2(h2f2(hdO[mt][nt][1]), bv, K, RS[mt * 2 + 1]);
        }
    }
}

__global__ __launch_bounds__(256, 1) void kC4() {
    extern __shared__ char sm[];
    uint32_t sb = smem_u32b(sm);
    int tid = threadIdx.x, lane = tid & 31, wid = tid >> 5;
    int warp_m = wid >> 2, warp_n = wid & 3;

    const char* gz = (const char*)g_z16;
    const char* gw = (const char*)g_w16;

    ExpC K;
    K.L2E2 = pk2(L2E, L2E);
    K.MG2  = pk2(12582912.0f, 12582912.0f);
    K.NEG1 = pk2(-1.0f, -1.0f);
    K.C4   = pk2(0.009618129107f, 0.009618129107f);
    K.C3   = pk2(0.055504108664f, 0.055504108664f);
    K.C2   = pk2(0.240226506959f, 0.240226506959f);
    K.C1   = pk2(0.693147180560f, 0.693147180560f);
    K.ONE2 = pk2(1.0f, 1.0f);

    uint32_t aBase = sb + SM_A + (uint32_t)(warp_m * 64 + (lane & 15)) * PITCH + (uint32_t)(lane >> 4) * 16;
    uint32_t bRowOff = (uint32_t)(warp_n * 32 + (lane & 7)) * PITCH + (uint32_t)((lane >> 3) & 1) * 16;

    int cta = blockIdx.x;
    int u0 = (cta * NUNITS) / NCTA;
    int u1 = ((cta + 1) * NUNITS) / NCTA;

    uint32_t hdA[4][4][2], hdB[4][4][2];
    u64t RS[8];

    int u = u0;
    while (u < u1) {
        int mt   = u / NGRP;
        int uend = min(u1, (mt + 1) * NGRP);
        int g0   = u - mt * NGRP;
        int ch0  = g0 * GRP;
        int nch  = (uend - mt * NGRP) * GRP - ch0;

        #pragma unroll
        for (int k = 0; k < 8; k++) RS[k] = 0ULL;

        // segment prologue: A tile + B(ch0) -> group0; B(ch0+1) -> group1
        #pragma unroll
        for (int i = 0; i < 8; i++) {
            int idx = tid + i * 256, row = idx >> 4, part = idx & 15;
            cpa16(sb + SM_A + row * PITCH + part * 16,
                  gz + ((size_t)mt << 15) + ((size_t)idx << 4));
        }
        #pragma unroll
        for (int i = 0; i < 8; i++) {
            int idx = tid + i * 256, row = idx >> 4, part = idx & 15;
            cpa16(sb + SM_B0 + row * PITCH + part * 16,
                  gw + ((size_t)ch0 << 15) + ((size_t)idx << 4));
        }
        CP_COMMIT();
        #pragma unroll
        for (int i = 0; i < 8; i++) {
            int idx = tid + i * 256, row = idx >> 4, part = idx & 15;
            cpa16(sb + SM_B0 + 34816 + row * PITCH + part * 16,
                  gw + ((size_t)(ch0 + 1) << 15) + ((size_t)idx << 4));
        }
        CP_COMMIT();

        CP_WAIT1();
        __syncthreads();
        do_chunk<false>(aBase, sb + SM_B0 + bRowOff, hdA, hdB, g_bl2, warp_n, lane, K, RS);
        __syncthreads();
        if (2 < nch) {
            #pragma unroll
            for (int i = 0; i < 8; i++) {
                int idx = tid + i * 256, row = idx >> 4, part = idx & 15;
                cpa16(sb + SM_B0 + row * PITCH + part * 16,
                      gw + ((size_t)(ch0 + 2) << 15) + ((size_t)idx << 4));
            }
        }
        CP_COMMIT();

        #pragma unroll 1
        for (int c = 0; c < nch; c++) {
            int p = c & 1;
            const float* bl2c = g_bl2 + (size_t)(ch0 + c) * 128;
            if (c + 1 < nch) {
                CP_WAIT1();
                __syncthreads();
                uint32_t Bb = sb + SM_B0 + (uint32_t)(p ^ 1) * 34816 + bRowOff;
                if (p == 0) do_chunk<true>(aBase, Bb, hdB, hdA, bl2c, warp_n, lane, K, RS);
                else        do_chunk<true>(aBase, Bb, hdA, hdB, bl2c, warp_n, lane, K, RS);
                __syncthreads();
                if (c + 3 < nch) {
                    #pragma unroll
                    for (int i = 0; i < 8; i++) {
                        int idx = tid + i * 256, row = idx >> 4, part = idx & 15;
                        cpa16(sb + SM_B0 + (uint32_t)(p ^ 1) * 34816 + row * PITCH + part * 16,
                              gw + ((size_t)(ch0 + c + 3) << 15) + ((size_t)idx << 4));
                    }
                }
                CP_COMMIT();
            } else {
                if (p == 0) epi_only(hdA, bl2c, warp_n, lane, K, RS);
                else        epi_only(hdB, bl2c, warp_n, lane, K, RS);
            }
        }

        // deterministic flush: slot = (g0, warp_n)
        #pragma unroll
        for (int k = 0; k < 8; k++) {
            float lo, hi;
            asm("mov.b64 {%0, %1}, %2;" : "=f"(lo), "=f"(hi) : "l"(RS[k]));
            float s = lo + hi;
            s += __shfl_xor_sync(0xffffffffu, s, 1);
            s += __shfl_xor_sync(0xffffffffu, s, 2);
            if ((lane & 3) == 0) {
                int mtt = k >> 1, rp = k & 1;
                int row = mt * 128 + warp_m * 64 + mtt * 16 + (lane >> 2) + rp * 8;
                g_epsG[(size_t)(g0 * 4 + warp_n) * ROWS + row] = s;
            }
        }
        u = uend;
    }
}

// ================= Kernel F: merge =================
__global__ void kF(float* __restrict__ out) {
    int r = blockIdx.x * 256 + threadIdx.x;
    float se = 0.f;
    #pragma unroll 4
    for (int s = 0; s < NSLOT; s++) se += g_epsG[(size_t)s * ROWS + r];
    out[r] = g_tg[r] - 30.f - logf(se);
}

// ================= launch =================
extern "C" void kernel_launch(void* const* d_in, const int* in_sizes, int n_in,
                              void* d_out, int out_size) {
    const float* latent = (const float*)d_in[0];
    const float* vw     = (const float*)d_in[1];
    const float* vb     = (const float*)d_in[2];
    const int*   zi     = (const int*)d_in[3];
    const int*   y      = (const int*)d_in[4];
    float* out = (float*)d_out;

    static cudaStream_t s1 = nullptr;
    static cudaEvent_t e0, eW, eZ, eT;
    if (!s1) {
        cudaStreamCreateWithFlags(&s1, cudaStreamNonBlocking);
        cudaEventCreateWithFlags(&e0, cudaEventDisableTiming);
        cudaEventCreateWithFlags(&eW, cudaEventDisableTiming);
        cudaEventCreateWithFlags(&eZ, cudaEventDisableTiming);
        cudaEventCreateWithFlags(&eT, cudaEventDisableTiming);
        cudaFuncSetAttribute(kA12, cudaFuncAttributeMaxDynamicSharedMemorySize, KA12_SMEM);
        cudaFuncSetAttribute(kC4, cudaFuncAttributeMaxDynamicSharedMemorySize, SMEM_KC);
    }

    // fork: vocab fp16 convert + bl2 precompute + eps zero on side stream
    cudaEventRecord(e0, 0);
    cudaStreamWaitEvent(s1, e0, 0);
    kWc<<<2000, 256, 0, s1>>>(vw, vb);
    cudaEventRecord(eW, s1);

    // main chain
    kA12<<<B_, 256, KA12_SMEM>>>(latent, zi);
    kBS<<<dim3(B_, 4), 256>>>();
    kB2<<<256, 256>>>(latent, zi);

    // fork: exact target logits overlap with kC4
    cudaEventRecord(eZ, 0);
    cudaStreamWaitEvent(s1, eZ, 0);
    kT<<<1024, 256, 0, s1>>>(vw, vb, y);
    cudaEventRecord(eT, s1);

    // join vocab convert, run persistent fused GEMM
    cudaStreamWaitEvent(0, eW, 0);
    kC4<<<NCTA, 256, SMEM_KC>>>();

    cudaStreamWaitEvent(0, eT, 0);
    kF<<<32, 256>>>(out);
}

// round 12
// speedup vs baseline: 1.0057x; 1.0057x over previous
#include <cuda_runtime.h>
#include <cuda_fp16.h>
#include <math_constants.h>
#include <cstdint>

// ---------------- problem constants ----------------
#define B_     32
#define S_     64
#define E_     128
#define TSTEP  256
#define VOCAB  32000
#define ROWS   8192
#define NCHUNK 250            // vocab chunks of 128
#define NGRP   250            // units per mtile (GRP=1: unit == chunk)
#define NUNITS 16000          // 64 mtiles * 250
#define NCTA   148
#define NSLOT  NCTA           // one partial slot per CTA
#define L2E    1.4426950408889634f

// ---------------- scratch ----------------
__device__ float    g_xtran [B_*S_*S_];
__device__ float    g_A     [B_*TSTEP*S_];
__device__ float    g_zs    [ROWS*E_];
__device__ float    g_bl2   [VOCAB];             // bias*L2E + (127 - 30*L2E)
__device__ __align__(16) unsigned short g_w16[VOCAB*E_];
__device__ __align__(16) unsigned short g_z16[ROWS*E_];
__device__ __align__(16) float g_epsG[NSLOT*ROWS];
__device__ float    g_tg [ROWS];

// ---------------- helpers ----------------
__device__ __forceinline__ uint32_t smem_u32b(const void* p) {
    uint32_t a;
    asm("{ .reg .u64 t; cvta.to.shared.u64 t, %1; cvt.u32.u64 %0, t; }" : "=r"(a) : "l"(p));
    return a;
}
__device__ __forceinline__ void cpa16(uint32_t dst, const void* src) {
    asm volatile("cp.async.cg.shared.global [%0], [%1], 16;" :: "r"(dst), "l"(src));
}
#define CP_COMMIT() asm volatile("cp.async.commit_group;" ::: "memory")
#define CP_WAIT1()  asm volatile("cp.async.wait_group 1;" ::: "memory")
#define CP_WAIT0()  asm volatile("cp.async.wait_group 0;" ::: "memory")

__device__ __forceinline__ void ldm_x4(uint32_t addr, uint32_t& r0, uint32_t& r1, uint32_t& r2, uint32_t& r3) {
    asm volatile("ldmatrix.sync.aligned.m8n8.x4.shared.b16 {%0,%1,%2,%3}, [%4];"
        : "=r"(r0), "=r"(r1), "=r"(r2), "=r"(r3) : "r"(addr));
}
__device__ __forceinline__ void ldm_x2(uint32_t addr, uint32_t& r0, uint32_t& r1) {
    asm volatile("ldmatrix.sync.aligned.m8n8.x2.shared.b16 {%0,%1}, [%2];"
        : "=r"(r0), "=r"(r1) : "r"(addr));
}
// fp16-accumulate HMMA (2 result regs)
__device__ __forceinline__ void mma16816h(uint32_t* d, const uint32_t* a, const uint32_t* b) {
    asm volatile("mma.sync.aligned.m16n8k16.row.col.f16.f16.f16.f16 "
        "{%0,%1}, {%2,%3,%4,%5}, {%6,%7}, {%0,%1};"
        : "+r"(d[0]), "+r"(d[1])
        : "r"(a[0]), "r"(a[1]), "r"(a[2]), "r"(a[3]), "r"(b[0]), "r"(b[1]));
}

typedef unsigned long long u64t;
__device__ __forceinline__ u64t pk2(float lo, float hi) {
    u64t r; asm("mov.b64 %0, {%1, %2};" : "=l"(r) : "f"(lo), "f"(hi)); return r;
}
__device__ __forceinline__ u64t fma2v(u64t a, u64t b, u64t c) {
    u64t r; asm volatile("fma.rn.f32x2 %0, %1, %2, %3;" : "=l"(r) : "l"(a), "l"(b), "l"(c)); return r;
}
__device__ __forceinline__ u64t h2f2(uint32_t h) {
    __half2 hh = *(__half2*)&h;
    float2 f = __half22float2(hh);
    u64t r; asm("mov.b64 %0, {%1, %2};" : "=l"(r) : "f"(f.x), "f"(f.y));
    return r;
}

struct ExpC {
    u64t L2E2, MG2, NEG1, C4, C3, C2, C1, ONE2;
};
// packed exp(l-30) accumulate; bl2 pre-biased: bias*L2E + (127 - 30*L2E)
__device__ __forceinline__ void expacc2(u64t acc, u64t bl2, const ExpC& K, u64t& rs) {
    u64t y = fma2v(acc, K.L2E2, bl2);
    u64t t = fma2v(y, K.ONE2, K.MG2);        // y + magic
    u64t n = fma2v(K.MG2, K.NEG1, t);        // t - magic
    u64t f = fma2v(n, K.NEG1, y);            // y - n
    u64t p = fma2v(K.C4, f, K.C3);
    p = fma2v(p, f, K.C2);
    p = fma2v(p, f, K.C1);
    p = fma2v(p, f, K.ONE2);
    uint32_t t0, t1;
    asm("mov.b64 {%0, %1}, %2;" : "=r"(t0), "=r"(t1) : "l"(t));
    t0 <<= 23; t1 <<= 23;
    u64t sc; asm("mov.b64 %0, {%1, %2};" : "=l"(sc) : "r"(t0), "r"(t1));
    rs = fma2v(p, sc, rs);
}

// ================= Kernel A12: scores + softmax + att0 (fused) =================
#define KA12_SMEM ((8256 + 4160) * 4)
__global__ __launch_bounds__(256) void kA12(const float* __restrict__ latent,
                                            const int* __restrict__ zi) {
    extern __shared__ float s[];
    float* xkS = s;            // 64 x 129
    float* scS = s + 8256;     // 64 x 65 (scores, [s][t])
    __shared__ float smv[64];
    int b = blockIdx.x, tid = threadIdx.x;
    const float* xq = latent + (size_t)zi[(b >> 2)]     * 32768 + (size_t)(b & 3) * 8192;
    const float* xk = latent + (size_t)zi[8 + (b >> 2)] * 32768 + (size_t)(b & 3) * 8192;

    for (int idx = tid; idx < 8192; idx += 256)
        xkS[(idx >> 7) * 129 + (idx & 127)] = __ldg(xk + idx);
    __syncthreads();

    int t = tid & 63, sg = tid >> 6;
    for (int i = 0; i < 16; i++) {
        int ss = sg + 4 * i;
        float a0 = 0.f, a1 = 0.f, a2 = 0.f, a3 = 0.f;
        const float4* qp = (const float4*)(xq + ss * 128);
        #pragma unroll 8
        for (int e4 = 0; e4 < 32; e4++) {
            float4 q = __ldg(qp + e4);
            const float* kp = &xkS[t * 129 + e4 * 4];
            a0 = fmaf(q.x, kp[0], a0);
            a1 = fmaf(q.y, kp[1], a1);
            a2 = fmaf(q.z, kp[2], a2);
            a3 = fmaf(q.w, kp[3], a3);
        }
        scS[ss * 65 + t] = ((a0 + a1) + (a2 + a3)) * 0.08838834764831843f;
    }
    __syncthreads();

    // column softmax over s (threads 0..63, one column each)
    if (tid < 64) {
        float mx = -CUDART_INF_F;
        for (int ss = 0; ss < 64; ss++) mx = fmaxf(mx, scS[ss * 65 + tid]);
        float sum = 0.f;
        for (int ss = 0; ss < 64; ss++) {
            float e = __expf(scS[ss * 65 + tid] - mx);
            scS[ss * 65 + tid] = e;
            sum += e;
        }
        float inv = 1.f / sum;
        for (int ss = 0; ss < 64; ss++)
            g_xtran[b * 4096 + ss * 64 + tid] = scS[ss * 65 + tid] * inv;
    }

    // att0 = softmax over s of xi[b][s][0]
    const float* ip = latent + (size_t)zi[24 + (b >> 2)] * 32768 + (size_t)(b & 3) * 8192;
    float xi = 0.f;
    if (tid < 64) { xi = __ldg(ip + tid * 128); smv[tid] = xi; }
    __syncthreads();
    float m2 = -CUDART_INF_F;
    if (tid < 64) { for (int ss = 0; ss < 64; ss++) m2 = fmaxf(m2, smv[ss]); }
    float e2 = (tid < 64) ? __expf(xi - m2) : 0.f;
    __syncthreads();
    if (tid < 64) smv[tid] = e2;
    __syncthreads();
    if (tid < 64) {
        float su = 0.f;
        for (int ss = 0; ss < 64; ss++) su += smv[ss];
        g_A[(size_t)b * 16384 + tid] = e2 / su;   // A[0] = att0
    }
}

// ---- 64-dot with 8 independent accumulator chains (ILP 8) ----
__device__ __forceinline__ float dot64x(const float* __restrict__ row, const float* mcol) {
    float a0=0.f,a1=0.f,a2=0.f,a3=0.f,a4=0.f,a5=0.f,a6=0.f,a7=0.f;
    #pragma unroll
    for (int ss = 0; ss < 64; ss += 8) {
        float4 x = *(const float4*)&row[ss];
        float4 y = *(const float4*)&row[ss + 4];
        a0 = fmaf(x.x, mcol[ss+0], a0);
        a1 = fmaf(x.y, mcol[ss+1], a1);
        a2 = fmaf(x.z, mcol[ss+2], a2);
        a3 = fmaf(x.w, mcol[ss+3], a3);
        a4 = fmaf(y.x, mcol[ss+4], a4);
        a5 = fmaf(y.y, mcol[ss+5], a5);
        a6 = fmaf(y.z, mcol[ss+6], a6);
        a7 = fmaf(y.w, mcol[ss+7], a7);
    }
    return ((a0 + a1) + (a2 + a3)) + ((a4 + a5) + (a6 + a7));
}

// ================= Kernel B1v3: log-doubling scan (proven R10 version) =================
#define KB1_SMEM ((4352*2 + 16384) * 4)
__global__ __launch_bounds__(512) void kB1v3() {
    extern __shared__ float s[];
    float* M0 = s;                 // 64 x 68
    float* M1 = s + 4352;
    float* A  = s + 8704;          // 256 x 64
    int b = blockIdx.x, tid = threadIdx.x;
    int col = tid & 63, rg = tid >> 6;     // rg in 0..7

    for (int i = tid; i < 4096; i += 512)
        M0[(i >> 6) * 68 + (i & 63)] = g_xtran[b * 4096 + i];
    if (tid < 64) A[tid] = g_A[(size_t)b * 16384 + tid];
    __syncthreads();

    float* Mp = M0; float* Mq = M1;
    int cur = 1;
    #pragma unroll 1
    for (int it = 0; it < 8; it++) {
        float mcol[64];
        #pragma unroll
        for (int ss = 0; ss < 64; ss++) mcol[ss] = Mp[ss * 68 + col];
        if (it < 7) {
            #pragma unroll 2
            for (int r = rg; r < 64; r += 8)
                Mq[r * 68 + col] = dot64x(Mp + r * 68, mcol);
        }
        #pragma unroll 2
        for (int r = rg; r < cur; r += 8)
            A[(cur + r) * 64 + col] = dot64x(A + r * 64, mcol);
        __syncthreads();
        float* t = Mp; Mp = Mq; Mq = t;
        cur <<= 1;
    }
    for (int i = tid; i < 4096; i += 512) {
        float4 v = *(const float4*)&A[i * 4];
        *(float4*)&g_A[(size_t)b * 16384 + (size_t)i * 4] = v;
    }
}

// ================= Kernel B2: zs = A * xv, + fp16 convert =================
__global__ __launch_bounds__(256) void kB2(const float* __restrict__ latent, const int* __restrict__ zi) {
    __shared__ float As[2048];
    __shared__ float xvS[8192];
    int b = blockIdx.x >> 3, tb = blockIdx.x & 7;
    int tid = threadIdx.x;
    const float* xv = latent + (size_t)zi[16 + (b >> 2)] * 32768 + (size_t)(b & 3) * 8192;
    for (int i = tid; i < 8192; i += 256) xvS[i] = __ldg(xv + i);
    for (int i = tid; i < 2048; i += 256) As[i] = g_A[(size_t)(b * 256 + tb * 32) * 64 + i];
    __syncthreads();
    int e = tid & 127, h = tid >> 7;
    for (int i = 0; i < 16; i++) {
        int tl = h * 16 + i;
        float a0 = 0.f, a1 = 0.f, a2 = 0.f, a3 = 0.f;
        #pragma unroll
        for (int s2 = 0; s2 < 64; s2 += 4) {
            a0 = fmaf(As[tl * 64 + s2 + 0], xvS[(s2 + 0) * 128 + e], a0);
            a1 = fmaf(As[tl * 64 + s2 + 1], xvS[(s2 + 1) * 128 + e], a1);
            a2 = fmaf(As[tl * 64 + s2 + 2], xvS[(s2 + 2) * 128 + e], a2);
            a3 = fmaf(As[tl * 64 + s2 + 3], xvS[(s2 + 3) * 128 + e], a3);
        }
        float acc = (a0 + a1) + (a2 + a3);
        size_t row = (size_t)b * 256 + tb * 32 + tl;
        g_zs[row * 128 + e] = acc;
        g_z16[row * 128 + e] = __half_as_ushort(__float2half(acc));
    }
}

// ================= Kernel Wc: vocab fp16 + bl2 precompute + g_epsG zero =================
__global__ __launch_bounds__(256) void kWc(const float* __restrict__ vw,
                                           const float* __restrict__ vb) {
    int t = blockIdx.x * 256 + threadIdx.x;
    size_t i = (size_t)t * 8;
    float4 a = *(const float4*)(vw + i);
    float4 b = *(const float4*)(vw + i + 4);
    __half2 h0 = __floats2half2_rn(a.x, a.y);
    __half2 h1 = __floats2half2_rn(a.z, a.w);
    __half2 h2 = __floats2half2_rn(b.x, b.y);
    __half2 h3 = __floats2half2_rn(b.z, b.w);
    uint4 o;
    o.x = *(uint32_t*)&h0; o.y = *(uint32_t*)&h1;
    o.z = *(uint32_t*)&h2; o.w = *(uint32_t*)&h3;
    *(uint4*)(g_w16 + i) = o;
    if (t < VOCAB) g_bl2[t] = fmaf(__ldg(vb + t), L2E, 127.0f - 30.f * L2E);
    if (t < (NSLOT * ROWS) / 4) {
        float4 z = {0.f, 0.f, 0.f, 0.f};
        ((float4*)g_epsG)[t] = z;
    }
}

// ================= Kernel T: exact fp32 target logits =================
__global__ __launch_bounds__(256) void kT(const float* __restrict__ vw,
                                          const float* __restrict__ vb,
                                          const int*   __restrict__ y) {
    int r = blockIdx.x * 8 + (threadIdx.x >> 5);
    int lane = threadIdx.x & 31;
    int t = __ldg(y + r);
    float4 z = *(const float4*)(g_zs + (size_t)r * 128 + lane * 4);
    float4 w = *(const float4*)(vw + (size_t)t * 128 + lane * 4);
    float d = z.x * w.x + z.y * w.y + z.z * w.z + z.w * w.w;
    #pragma unroll
    for (int off = 16; off; off >>= 1) d += __shfl_xor_sync(0xffffffffu, d, off);
    if (lane == 0) g_tg[r] = d + __ldg(vb + t);
}

// ================= Kernel C4: persistent chunk-balanced HMMA + poly-exp ==========
#define PITCH   272
#define SM_A    0
#define SM_B0   34816
#define SMEM_KC 104448

template<bool DO_EPI>
__device__ __forceinline__ void do_chunk(uint32_t aBase, uint32_t Bbase,
                                         uint32_t (&hdN)[4][4][2],
                                         uint32_t (&hdO)[4][4][2],
                                         const float* __restrict__ bl2c,
                                         int warp_n, int lane,
                                         const ExpC& K, u64t (&RS)[8]) {
    #pragma unroll
    for (int mt = 0; mt < 4; mt++)
        #pragma unroll
        for (int nt = 0; nt < 4; nt++) { hdN[mt][nt][0] = 0u; hdN[mt][nt][1] = 0u; }

    u64t bv[4];
    if (DO_EPI) {
        #pragma unroll
        for (int nt = 0; nt < 4; nt++)
            bv[nt] = *(const u64t*)&bl2c[warp_n * 32 + nt * 8 + (lane & 3) * 2];
    }

    #pragma unroll
    for (int ks = 0; ks < 8; ks++) {
        uint32_t a[4][4], b[4][2];
        #pragma unroll
        for (int mt = 0; mt < 4; mt++)
            ldm_x4(aBase + (uint32_t)(mt * 16) * PITCH + (uint32_t)(ks * 32),
                   a[mt][0], a[mt][1], a[mt][2], a[mt][3]);
        #pragma unroll
        for (int nt = 0; nt < 4; nt++)
            ldm_x2(Bbase + (uint32_t)(nt * 8) * PITCH + (uint32_t)(ks * 32),
                   b[nt][0], b[nt][1]);
        #pragma unroll
        for (int mt = 0; mt < 4; mt++)
            #pragma unroll
            for (int nt = 0; nt < 4; nt++)
                mma16816h(hdN[mt][nt], a[mt], b[nt]);
        if (DO_EPI) {
            #pragma unroll
            for (int f = ks * 2; f < ks * 2 + 2; f++) {
                int mt = f >> 2, nt = f & 3;
                expacc2(h2f2(hdO[mt][nt][0]), bv[nt], K, RS[mt * 2 + 0]);
                expacc2(h2f2(hdO[mt][nt][1]), bv[nt], K, RS[mt * 2 + 1]);
            }
        }
    }
}

__device__ __forceinline__ void epi_only(uint32_t (&hdO)[4][4][2],
                                         const float* __restrict__ bl2c,
                                         int warp_n, int lane,
                                         const ExpC& K, u64t (&RS)[8]) {
    #pragma unroll
    for (int nt = 0; nt < 4; nt++) {
        u64t bv = *(const u64t*)&bl2c[warp_n * 32 + nt * 8 + (lane & 3) * 2];
        #pragma unroll
        for (int mt = 0; mt < 4; mt++) {
            expacc2(h2f2(hdO[mt][nt][0]), bv, K, RS[mt * 2 + 0]);
            expacc2(h2f2(hdO[mt][nt][1]), bv, K, RS[mt * 2 + 1]);
        }
    }
}

__global__ __launch_bounds__(256, 1) void kC4() {
    extern __shared__ char sm[];
    __shared__ float redS[512];          // 128 rows x 4 warp_n partials
    uint32_t sb = smem_u32b(sm);
    int tid = threadIdx.x, lane = tid & 31, wid = tid >> 5;
    int warp_m = wid >> 2, warp_n = wid & 3;

    const char* gz = (const char*)g_z16;
    const char* gw = (const char*)g_w16;

    ExpC K;
    K.L2E2 = pk2(L2E, L2E);
    K.MG2  = pk2(12582912.0f, 12582912.0f);
    K.NEG1 = pk2(-1.0f, -1.0f);
    K.C4   = pk2(0.009618129107f, 0.009618129107f);
    K.C3   = pk2(0.055504108664f, 0.055504108664f);
    K.C2   = pk2(0.240226506959f, 0.240226506959f);
    K.C1   = pk2(0.693147180560f, 0.693147180560f);
    K.ONE2 = pk2(1.0f, 1.0f);

    uint32_t aBase = sb + SM_A + (uint32_t)(warp_m * 64 + (lane & 15)) * PITCH + (uint32_t)(lane >> 4) * 16;
    uint32_t bRowOff = (uint32_t)(warp_n * 32 + (lane & 7)) * PITCH + (uint32_t)((lane >> 3) & 1) * 16;

    int cta = blockIdx.x;
    int u0 = (int)(((long long)cta * NUNITS) / NCTA);
    int u1 = (int)(((long long)(cta + 1) * NUNITS) / NCTA);

    uint32_t hdA[4][4][2], hdB[4][4][2];
    u64t RS[8];

    int u = u0;
    while (u < u1) {
        int mt   = u / NGRP;
        int uend = min(u1, (mt + 1) * NGRP);
        int ch0  = u - mt * NGRP;
        int nch  = uend - u;
        int ch1  = (nch >= 2) ? (ch0 + 1) : ch0;   // clamp: never read past chunk 249

        #pragma unroll
        for (int k = 0; k < 8; k++) RS[k] = 0ULL;

        // drain any unconsumed cp.async groups from the previous segment
        CP_WAIT0();

        // segment prologue: A tile + B(ch0) -> buf0; B(ch1) -> buf1
        #pragma unroll
        for (int i = 0; i < 8; i++) {
            int idx = tid + i * 256, row = idx >> 4, part = idx & 15;
            cpa16(sb + SM_A + row * PITCH + part * 16,
                  gz + ((size_t)mt << 15) + ((size_t)idx << 4));
        }
        #pragma unroll
        for (int i = 0; i < 8; i++) {
            int idx = tid + i * 256, row = idx >> 4, part = idx & 15;
            cpa16(sb + SM_B0 + row * PITCH + part * 16,
                  gw + ((size_t)ch0 << 15) + ((size_t)idx << 4));
        }
        CP_COMMIT();
        #pragma unroll
        for (int i = 0; i < 8; i++) {
            int idx = tid + i * 256, row = idx >> 4, part = idx & 15;
            cpa16(sb + SM_B0 + 34816 + row * PITCH + part * 16,
                  gw + ((size_t)ch1 << 15) + ((size_t)idx << 4));
        }
        CP_COMMIT();

        CP_WAIT1();
        __syncthreads();
        do_chunk<false>(aBase, sb + SM_B0 + bRowOff, hdA, hdB, g_bl2, warp_n, lane, K, RS);
        __syncthreads();
        if (2 < nch) {
            #pragma unroll
            for (int i = 0; i < 8; i++) {
                int idx = tid + i * 256, row = idx >> 4, part = idx & 15;
                cpa16(sb + SM_B0 + row * PITCH + part * 16,
                      gw + ((size_t)(ch0 + 2) << 15) + ((size_t)idx << 4));
            }
        }
        CP_COMMIT();

        #pragma unroll 1
        for (int c = 0; c < nch; c++) {
            int p = c & 1;
            const float* bl2c = g_bl2 + (size_t)(ch0 + c) * 128;
            if (c + 1 < nch) {
                CP_WAIT1();
                __syncthreads();
                uint32_t Bb = sb + SM_B0 + (uint32_t)(p ^ 1) * 34816 + bRowOff;
                if (p == 0) do_chunk<true>(aBase, Bb, hdB, hdA, bl2c, warp_n, lane, K, RS);
                else        do_chunk<true>(aBase, Bb, hdA, hdB, bl2c, warp_n, lane, K, RS);
                __syncthreads();
                if (c + 3 < nch) {
                    #pragma unroll
                    for (int i = 0; i < 8; i++) {
                        int idx = tid + i * 256, row = idx >> 4, part = idx & 15;
                        cpa16(sb + SM_B0 + (uint32_t)(p ^ 1) * 34816 + row * PITCH + part * 16,
                              gw + ((size_t)(ch0 + c + 3) << 15) + ((size_t)idx << 4));
                    }
                }
                CP_COMMIT();
            } else {
                if (p == 0) epi_only(hdA, bl2c, warp_n, lane, K, RS);
                else        epi_only(hdB, bl2c, warp_n, lane, K, RS);
            }
        }

        // flush: reduce 4 warp_n partials in smem, one slot per CTA
        #pragma unroll
        for (int k = 0; k < 8; k++) {
            float lo, hi;
            asm("mov.b64 {%0, %1}, %2;" : "=f"(lo), "=f"(hi) : "l"(RS[k]));
            float sv = lo + hi;
            sv += __shfl_xor_sync(0xffffffffu, sv, 1);
            sv += __shfl_xor_sync(0xffffffffu, sv, 2);
            if ((lane & 3) == 0) {
                int mtt = k >> 1, rp = k & 1;
                int local = warp_m * 64 + mtt * 16 + (lane >> 2) + rp * 8;
                redS[local * 4 + warp_n] = sv;
            }
        }
        __syncthreads();
        if (tid < 128) {
            float v = (redS[tid * 4] + redS[tid * 4 + 1]) + (redS[tid * 4 + 2] + redS[tid * 4 + 3]);
            g_epsG[(size_t)cta * ROWS + mt * 128 + tid] = v;
        }
        __syncthreads();
        u = uend;
    }
}

// ================= Kernel F: merge =================
__global__ void kF(float* __restrict__ out) {
    int r = blockIdx.x * 256 + threadIdx.x;
    float se = 0.f;
    #pragma unroll 4
    for (int s = 0; s < NSLOT; s++) se += g_epsG[(size_t)s * ROWS + r];
    out[r] = g_tg[r] - 30.f - logf(se);
}

// ================= launch =================
extern "C" void kernel_launch(void* const* d_in, const int* in_sizes, int n_in,
                              void* d_out, int out_size) {
    const float* latent = (const float*)d_in[0];
    const float* vw     = (const float*)d_in[1];
    const float* vb     = (const float*)d_in[2];
    const int*   zi     = (const int*)d_in[3];
    const int*   y      = (const int*)d_in[4];
    float* out = (float*)d_out;

    static cudaStream_t s1 = nullptr;
    static cudaEvent_t e0, eW, eZ, eT;
    if (!s1) {
        cudaStreamCreateWithFlags(&s1, cudaStreamNonBlocking);
        cudaEventCreateWithFlags(&e0, cudaEventDisableTiming);
        cudaEventCreateWithFlags(&eW, cudaEventDisableTiming);
        cudaEventCreateWithFlags(&eZ, cudaEventDisableTiming);
        cudaEventCreateWithFlags(&eT, cudaEventDisableTiming);
        cudaFuncSetAttribute(kA12, cudaFuncAttributeMaxDynamicSharedMemorySize, KA12_SMEM);
        cudaFuncSetAttribute(kB1v3, cudaFuncAttributeMaxDynamicSharedMemorySize, KB1_SMEM);
        cudaFuncSetAttribute(kC4, cudaFuncAttributeMaxDynamicSharedMemorySize, SMEM_KC);
    }

    // fork: vocab fp16 convert + bl2 precompute + eps zero on side stream
    cudaEventRecord(e0, 0);
    cudaStreamWaitEvent(s1, e0, 0);
    kWc<<<2000, 256, 0, s1>>>(vw, vb);
    cudaEventRecord(eW, s1);

    // main chain
    kA12<<<B_, 256, KA12_SMEM>>>(latent, zi);
    kB1v3<<<B_, 512, KB1_SMEM>>>();
    kB2<<<256, 256>>>(latent, zi);

    // fork: exact target logits overlap with kC4
    cudaEventRecord(eZ, 0);
    cudaStreamWaitEvent(s1, eZ, 0);
    kT<<<1024, 256, 0, s1>>>(vw, vb, y);
    cudaEventRecord(eT, s1);

    // join vocab convert, run persistent fused GEMM
    cudaStreamWaitEvent(0, eW, 0);
    kC4<<<NCTA, 256, SMEM_KC>>>();

    cudaStreamWaitEvent(0, eT, 0);
    kF<<<32, 256>>>(out);
}